// round 4
// baseline (speedup 1.0000x reference)
#include <cuda_runtime.h>
#include <cuda_bf16.h>

// ---------------------------------------------------------------------------
// QuantumLayer: 4 qubits, 2 variational layers, B = 1e6.
//
// z_q(b) = r(b)^T A_q r(b),  r = tensor prod of (cos(x_q/2), sin(x_q/2)).
// Half-angle identities turn this into an 81-monomial contraction over the
// per-qubit basis (1, cos x_q, sin x_q):
//     z_q(b) = sum_t T_q[t] * prod_q basis_{t_q}(x_q)
// T[81][4] depends only on weights; computed by a 1-block setup kernel,
// then copied into __constant__ memory (async D2D memcpy node). The main
// kernel reads T via the uniform/constant datapath (LDCU / UR operands) —
// zero shared-memory traffic, 2 samples/thread, packed fma.rn.f32x2.
// ---------------------------------------------------------------------------

#define DIM 16

__device__ float4 g_T4[81];        // staging: (T0,T1,T2,T3) per monomial
__constant__ ulonglong2 cT[81];    // .x = packed (T0,T1), .y = packed (T2,T3)

// ---------------------------------------------------------------------------
// Setup kernel: one block, 256 threads, three phases.
// ---------------------------------------------------------------------------
__global__ void setup_kernel(const float* __restrict__ weights) {
    __shared__ float sWre[DIM][DIM];   // [j][k]
    __shared__ float sWim[DIM][DIM];
    __shared__ float sA[4][256];       // A_q[k*16+k']
    int tid = threadIdx.x;

    // ---- Phase 1: threads 0-15 evolve column k of U, fold encoding phase ----
    if (tid < DIM) {
        int k = tid;
        float cr[DIM], ci[DIM];
#pragma unroll
        for (int j = 0; j < DIM; j++) { cr[j] = (j == k) ? 1.0f : 0.0f; ci[j] = 0.0f; }

        for (int l = 0; l < 2; l++) {
            for (int q = 0; q < 4; q++) {
                const int mask = 8 >> q;
                float thx = weights[(l * 4 + q) * 3 + 0];
                float thy = weights[(l * 4 + q) * 3 + 1];
                float thz = weights[(l * 4 + q) * 3 + 2];
                // RX = [[c, -i s], [-i s, c]]
                {
                    float c = cosf(0.5f * thx), s = sinf(0.5f * thx);
#pragma unroll
                    for (int rr = 0; rr < 8; rr++) {
                        int j0 = ((rr & ~(mask - 1)) << 1) | (rr & (mask - 1));
                        int j1 = j0 | mask;
                        float ar0 = cr[j0], ai0 = ci[j0], ar1 = cr[j1], ai1 = ci[j1];
                        cr[j0] = c * ar0 + s * ai1;
                        ci[j0] = c * ai0 - s * ar1;
                        cr[j1] = c * ar1 + s * ai0;
                        ci[j1] = c * ai1 - s * ar0;
                    }
                }
                // RY = [[c, -s], [s, c]]
                {
                    float c = cosf(0.5f * thy), s = sinf(0.5f * thy);
#pragma unroll
                    for (int rr = 0; rr < 8; rr++) {
                        int j0 = ((rr & ~(mask - 1)) << 1) | (rr & (mask - 1));
                        int j1 = j0 | mask;
                        float ar0 = cr[j0], ai0 = ci[j0], ar1 = cr[j1], ai1 = ci[j1];
                        cr[j0] = c * ar0 - s * ar1;
                        ci[j0] = c * ai0 - s * ai1;
                        cr[j1] = s * ar0 + c * ar1;
                        ci[j1] = s * ai0 + c * ai1;
                    }
                }
                // RZ = diag(e^{-i t/2}, e^{+i t/2})
                {
                    float c = cosf(0.5f * thz), s = sinf(0.5f * thz);
#pragma unroll
                    for (int rr = 0; rr < 8; rr++) {
                        int j0 = ((rr & ~(mask - 1)) << 1) | (rr & (mask - 1));
                        int j1 = j0 | mask;
                        float ar0 = cr[j0], ai0 = ci[j0], ar1 = cr[j1], ai1 = ci[j1];
                        cr[j0] = c * ar0 + s * ai0;
                        ci[j0] = c * ai0 - s * ar0;
                        cr[j1] = c * ar1 - s * ai1;
                        ci[j1] = c * ai1 + s * ar1;
                    }
                }
            }
            // CNOT ring (0,1),(1,2),(2,3),(3,0): row swaps in control=1 space
#pragma unroll
            for (int e = 0; e < 4; e++) {
                const int cm = 8 >> e, tm = 8 >> ((e + 1) & 3);
#pragma unroll
                for (int j = 0; j < DIM; j++) {
                    if ((j & cm) && !(j & tm)) {
                        int j2 = j ^ tm;
                        float tr = cr[j]; cr[j] = cr[j2]; cr[j2] = tr;
                        float ti = ci[j]; ci[j] = ci[j2]; ci[j2] = ti;
                    }
                }
            }
        }

        // Encoding phase (-i)^popc(k)
        int pc = __popc(k) & 3;
        float pr = (pc == 0) ? 1.0f : (pc == 2) ? -1.0f : 0.0f;
        float pi = (pc == 1) ? -1.0f : (pc == 3) ? 1.0f : 0.0f;
#pragma unroll
        for (int j = 0; j < DIM; j++) {
            sWre[j][k] = cr[j] * pr - ci[j] * pi;
            sWim[j][k] = cr[j] * pi + ci[j] * pr;
        }
    }
    __syncthreads();

    // ---- Phase 2: thread tid = k*16+k' computes A_q[k,k'] ----
    {
        int k = tid >> 4, kp = tid & 15;
        float a0 = 0.f, a1 = 0.f, a2 = 0.f, a3 = 0.f;
#pragma unroll
        for (int j = 0; j < DIM; j++) {
            float p = sWre[j][k] * sWre[j][kp] + sWim[j][k] * sWim[j][kp];
            a0 += (j & 8) ? -p : p;
            a1 += (j & 4) ? -p : p;
            a2 += (j & 2) ? -p : p;
            a3 += (j & 1) ? -p : p;
        }
        sA[0][tid] = a0; sA[1][tid] = a1; sA[2][tid] = a2; sA[3][tid] = a3;
    }
    __syncthreads();

    // ---- Phase 3: threads 0-80 compute T[t] ----
    if (tid < 81) {
        int t0 = tid / 27, t1 = (tid / 9) % 3, t2 = (tid / 3) % 3, t3 = tid % 3;
        int mix = 0, sgn = 0;
        if (t0 == 2) mix |= 8; else if (t0 == 1) sgn |= 8;
        if (t1 == 2) mix |= 4; else if (t1 == 1) sgn |= 4;
        if (t2 == 2) mix |= 2; else if (t2 == 1) sgn |= 2;
        if (t3 == 2) mix |= 1; else if (t3 == 1) sgn |= 1;

        float r0 = 0.f, r1 = 0.f, r2 = 0.f, r3 = 0.f;
#pragma unroll
        for (int k = 0; k < DIM; k++) {
            int idx = k * DIM + (k ^ mix);
            float s = (__popc(k & sgn) & 1) ? -1.0f : 1.0f;
            r0 += s * sA[0][idx];
            r1 += s * sA[1][idx];
            r2 += s * sA[2][idx];
            r3 += s * sA[3][idx];
        }
        const float sc = 1.0f / 16.0f;
        g_T4[tid] = make_float4(r0 * sc, r1 * sc, r2 * sc, r3 * sc);
    }
}

// ---------------------------------------------------------------------------
// Packed f32x2 helpers
// ---------------------------------------------------------------------------
__device__ __forceinline__ void ffma2(unsigned long long& d,
                                      unsigned long long a,
                                      unsigned long long b) {
    asm("fma.rn.f32x2 %0, %1, %2, %0;" : "+l"(d) : "l"(a), "l"(b));
}

__device__ __forceinline__ unsigned long long pack_dup(float v) {
    unsigned long long out;
    unsigned int u = __float_as_uint(v);
    asm("mov.b64 %0, {%1, %1};" : "=l"(out) : "r"(u));
    return out;
}

__device__ __forceinline__ void unpack2(unsigned long long v, float& lo, float& hi) {
    unsigned int a, b;
    asm("mov.b64 {%0, %1}, %2;" : "=r"(a), "=r"(b) : "l"(v));
    lo = __uint_as_float(a);
    hi = __uint_as_float(b);
}

// ---------------------------------------------------------------------------
// Main kernel: 2 samples per thread; factorized 81-monomial contraction.
// T read through the constant/uniform datapath (no shared memory at all).
// ---------------------------------------------------------------------------
__global__ void __launch_bounds__(128)
qlayer_kernel(const float4* __restrict__ in, float4* __restrict__ out, int nb) {
    int p = blockIdx.x * blockDim.x + threadIdx.x;   // pair index
    int b0 = 2 * p;
    if (b0 >= nb) return;
    bool hasB = (b0 + 1) < nb;

    float4 xA = in[b0];
    float4 xB = hasB ? in[b0 + 1] : xA;

    float cA0, sA0, cA1, sA1, cA2, sA2, cA3, sA3;
    __sincosf(xA.x, &sA0, &cA0);
    __sincosf(xA.y, &sA1, &cA1);
    __sincosf(xA.z, &sA2, &cA2);
    __sincosf(xA.w, &sA3, &cA3);
    float cB0, sB0, cB1, sB1, cB2, sB2, cB3, sB3;
    __sincosf(xB.x, &sB0, &cB0);
    __sincosf(xB.y, &sB1, &cB1);
    __sincosf(xB.z, &sB2, &cB2);
    __sincosf(xB.w, &sB3, &cB3);

    // ab[a], a = 3*t0 + t1 over basis (1, c, s) of qubits 0,1 (scalar)
    float abA[9] = { 1.f, cA1, sA1, cA0, cA0 * cA1, cA0 * sA1, sA0, sA0 * cA1, sA0 * sA1 };
    float abB[9] = { 1.f, cB1, sB1, cB0, cB0 * cB1, cB0 * sB1, sB0, sB0 * cB1, sB0 * sB1 };
    // cd[c], c = 3*t2 + t3, qubits 2,3 (packed dup — inner ffma2 operand)
    float cdAs[9] = { 1.f, cA3, sA3, cA2, cA2 * cA3, cA2 * sA3, sA2, sA2 * cA3, sA2 * sA3 };
    float cdBs[9] = { 1.f, cB3, sB3, cB2, cB2 * cB3, cB2 * sB3, sB2, sB2 * cB3, sB2 * sB3 };
    unsigned long long cdA[9], cdB[9];
#pragma unroll
    for (int c = 0; c < 9; c++) { cdA[c] = pack_dup(cdAs[c]); cdB[c] = pack_dup(cdBs[c]); }

    unsigned long long zA01 = 0ull, zA23 = 0ull, zB01 = 0ull, zB23 = 0ull;
#pragma unroll
    for (int a = 0; a < 9; a++) {
        unsigned long long vA01 = 0ull, vA23 = 0ull, vB01 = 0ull, vB23 = 0ull;
#pragma unroll
        for (int c = 0; c < 9; c++) {
            ulonglong2 w = cT[a * 9 + c];    // uniform -> LDCU / UR operands
            ffma2(vA01, w.x, cdA[c]);
            ffma2(vA23, w.y, cdA[c]);
            ffma2(vB01, w.x, cdB[c]);
            ffma2(vB23, w.y, cdB[c]);
        }
        unsigned long long aa = pack_dup(abA[a]);
        unsigned long long bb = pack_dup(abB[a]);
        ffma2(zA01, aa, vA01);
        ffma2(zA23, aa, vA23);
        ffma2(zB01, bb, vB01);
        ffma2(zB23, bb, vB23);
    }

    float z0, z1, z2, z3;
    unpack2(zA01, z0, z1);
    unpack2(zA23, z2, z3);
    out[b0] = make_float4(z0, z1, z2, z3);
    if (hasB) {
        unpack2(zB01, z0, z1);
        unpack2(zB23, z2, z3);
        out[b0 + 1] = make_float4(z0, z1, z2, z3);
    }
}

// ---------------------------------------------------------------------------
extern "C" void kernel_launch(void* const* d_in, const int* in_sizes, int n_in,
                              void* d_out, int out_size) {
    const float* inputs  = (const float*)d_in[0];
    const float* weights = (const float*)d_in[1];
    if (n_in >= 2 && in_sizes[0] == 24) {  // defensive: identify by size
        weights = (const float*)d_in[0];
        inputs  = (const float*)d_in[1];
    }
    int nb = out_size / 4;  // samples

    setup_kernel<<<1, 256>>>(weights);

    // Async D2D copy of the staged T tensor into constant memory.
    // (device-to-device memcpyAsync: graph-capture legal, no allocation)
    void* src = nullptr;
    cudaGetSymbolAddress(&src, g_T4);
    cudaMemcpyToSymbolAsync(cT, src, 81 * sizeof(ulonglong2), 0,
                            cudaMemcpyDeviceToDevice, 0);

    int pairs = (nb + 1) / 2;
    int threads = 128;
    int blocks = (pairs + threads - 1) / threads;
    qlayer_kernel<<<blocks, threads>>>((const float4*)inputs, (float4*)d_out, nb);
}

// round 5
// speedup vs baseline: 1.0740x; 1.0740x over previous
#include <cuda_runtime.h>
#include <cuda_bf16.h>

// ---------------------------------------------------------------------------
// QuantumLayer: 4 qubits, 2 variational layers, B = 1e6.
//
// z_q(b) = sum_{t in 3^4} T_q[t] * prod_q basis_{t_q}(x_q),
//   basis = (1, cos x_q, sin x_q);  T[81][4] depends only on weights.
// Setup kernel computes T and stores it straight into the __constant__
// backing store (pointer passed from host via cudaGetSymbolAddress) — no
// separate memcpy node. Main kernel: 4 samples/thread, outputs packed in
// fma.rn.f32x2 lanes, T read via the constant datapath.
// ---------------------------------------------------------------------------

#define DIM 16

__constant__ ulonglong2 cT[81];    // .x = packed (T0,T1), .y = packed (T2,T3)

// ---------------------------------------------------------------------------
// Setup kernel: one block, 256 threads, three phases. Writes T via t_out.
// ---------------------------------------------------------------------------
__global__ void setup_kernel(const float* __restrict__ weights,
                             float4* __restrict__ t_out) {
    __shared__ float sWre[DIM][DIM];   // [j][k]
    __shared__ float sWim[DIM][DIM];
    __shared__ float sA[4][256];       // A_q[k*16+k']
    int tid = threadIdx.x;

    // ---- Phase 1: threads 0-15 evolve column k of U, fold encoding phase ----
    if (tid < DIM) {
        int k = tid;
        float cr[DIM], ci[DIM];
#pragma unroll
        for (int j = 0; j < DIM; j++) { cr[j] = (j == k) ? 1.0f : 0.0f; ci[j] = 0.0f; }

        for (int l = 0; l < 2; l++) {
            for (int q = 0; q < 4; q++) {
                const int mask = 8 >> q;
                float thx = weights[(l * 4 + q) * 3 + 0];
                float thy = weights[(l * 4 + q) * 3 + 1];
                float thz = weights[(l * 4 + q) * 3 + 2];
                float c, s;
                // RX = [[c, -i s], [-i s, c]]
                __sincosf(0.5f * thx, &s, &c);
#pragma unroll
                for (int rr = 0; rr < 8; rr++) {
                    int j0 = ((rr & ~(mask - 1)) << 1) | (rr & (mask - 1));
                    int j1 = j0 | mask;
                    float ar0 = cr[j0], ai0 = ci[j0], ar1 = cr[j1], ai1 = ci[j1];
                    cr[j0] = c * ar0 + s * ai1;
                    ci[j0] = c * ai0 - s * ar1;
                    cr[j1] = c * ar1 + s * ai0;
                    ci[j1] = c * ai1 - s * ar0;
                }
                // RY = [[c, -s], [s, c]]
                __sincosf(0.5f * thy, &s, &c);
#pragma unroll
                for (int rr = 0; rr < 8; rr++) {
                    int j0 = ((rr & ~(mask - 1)) << 1) | (rr & (mask - 1));
                    int j1 = j0 | mask;
                    float ar0 = cr[j0], ai0 = ci[j0], ar1 = cr[j1], ai1 = ci[j1];
                    cr[j0] = c * ar0 - s * ar1;
                    ci[j0] = c * ai0 - s * ai1;
                    cr[j1] = s * ar0 + c * ar1;
                    ci[j1] = s * ai0 + c * ai1;
                }
                // RZ = diag(e^{-i t/2}, e^{+i t/2})
                __sincosf(0.5f * thz, &s, &c);
#pragma unroll
                for (int rr = 0; rr < 8; rr++) {
                    int j0 = ((rr & ~(mask - 1)) << 1) | (rr & (mask - 1));
                    int j1 = j0 | mask;
                    float ar0 = cr[j0], ai0 = ci[j0], ar1 = cr[j1], ai1 = ci[j1];
                    cr[j0] = c * ar0 + s * ai0;
                    ci[j0] = c * ai0 - s * ar0;
                    cr[j1] = c * ar1 - s * ai1;
                    ci[j1] = c * ai1 + s * ar1;
                }
            }
            // CNOT ring (0,1),(1,2),(2,3),(3,0): row swaps in control=1 space
#pragma unroll
            for (int e = 0; e < 4; e++) {
                const int cm = 8 >> e, tm = 8 >> ((e + 1) & 3);
#pragma unroll
                for (int j = 0; j < DIM; j++) {
                    if ((j & cm) && !(j & tm)) {
                        int j2 = j ^ tm;
                        float tr = cr[j]; cr[j] = cr[j2]; cr[j2] = tr;
                        float ti = ci[j]; ci[j] = ci[j2]; ci[j2] = ti;
                    }
                }
            }
        }

        // Encoding phase (-i)^popc(k)
        int pc = __popc(k) & 3;
        float pr = (pc == 0) ? 1.0f : (pc == 2) ? -1.0f : 0.0f;
        float pi = (pc == 1) ? -1.0f : (pc == 3) ? 1.0f : 0.0f;
#pragma unroll
        for (int j = 0; j < DIM; j++) {
            sWre[j][k] = cr[j] * pr - ci[j] * pi;
            sWim[j][k] = cr[j] * pi + ci[j] * pr;
        }
    }
    __syncthreads();

    // ---- Phase 2: thread tid = k*16+k' computes A_q[k,k'] ----
    {
        int k = tid >> 4, kp = tid & 15;
        float a0 = 0.f, a1 = 0.f, a2 = 0.f, a3 = 0.f;
#pragma unroll
        for (int j = 0; j < DIM; j++) {
            float p = sWre[j][k] * sWre[j][kp] + sWim[j][k] * sWim[j][kp];
            a0 += (j & 8) ? -p : p;
            a1 += (j & 4) ? -p : p;
            a2 += (j & 2) ? -p : p;
            a3 += (j & 1) ? -p : p;
        }
        sA[0][tid] = a0; sA[1][tid] = a1; sA[2][tid] = a2; sA[3][tid] = a3;
    }
    __syncthreads();

    // ---- Phase 3: threads 0-80 compute T[t], write to constant backing ----
    if (tid < 81) {
        int t0 = tid / 27, t1 = (tid / 9) % 3, t2 = (tid / 3) % 3, t3 = tid % 3;
        int mix = 0, sgn = 0;
        if (t0 == 2) mix |= 8; else if (t0 == 1) sgn |= 8;
        if (t1 == 2) mix |= 4; else if (t1 == 1) sgn |= 4;
        if (t2 == 2) mix |= 2; else if (t2 == 1) sgn |= 2;
        if (t3 == 2) mix |= 1; else if (t3 == 1) sgn |= 1;

        float r0 = 0.f, r1 = 0.f, r2 = 0.f, r3 = 0.f;
#pragma unroll
        for (int k = 0; k < DIM; k++) {
            int idx = k * DIM + (k ^ mix);
            float s = (__popc(k & sgn) & 1) ? -1.0f : 1.0f;
            r0 += s * sA[0][idx];
            r1 += s * sA[1][idx];
            r2 += s * sA[2][idx];
            r3 += s * sA[3][idx];
        }
        const float sc = 1.0f / 16.0f;
        t_out[tid] = make_float4(r0 * sc, r1 * sc, r2 * sc, r3 * sc);
    }
}

// ---------------------------------------------------------------------------
// Packed f32x2 helpers
// ---------------------------------------------------------------------------
__device__ __forceinline__ void ffma2(unsigned long long& d,
                                      unsigned long long a,
                                      unsigned long long b) {
    asm("fma.rn.f32x2 %0, %1, %2, %0;" : "+l"(d) : "l"(a), "l"(b));
}

__device__ __forceinline__ unsigned long long pack_dup(float v) {
    unsigned long long out;
    unsigned int u = __float_as_uint(v);
    asm("mov.b64 %0, {%1, %1};" : "=l"(out) : "r"(u));
    return out;
}

__device__ __forceinline__ void unpack2(unsigned long long v, float& lo, float& hi) {
    unsigned int a, b;
    asm("mov.b64 {%0, %1}, %2;" : "=r"(a), "=r"(b) : "l"(v));
    lo = __uint_as_float(a);
    hi = __uint_as_float(b);
}

// ---------------------------------------------------------------------------
// Main kernel: 4 samples per thread; factorized 81-monomial contraction.
// Per c-step: 1 LDC.128 + 8 ffma2 -> constant-port floor (8) never binds.
// ---------------------------------------------------------------------------
#define NS 4

__global__ void __launch_bounds__(128)
qlayer_kernel(const float4* __restrict__ in, float4* __restrict__ out, int nb) {
    int p = blockIdx.x * blockDim.x + threadIdx.x;
    int b0 = NS * p;
    if (b0 >= nb) return;

    float4 x[NS];
#pragma unroll
    for (int s = 0; s < NS; s++) {
        int b = b0 + s;
        x[s] = in[(b < nb) ? b : (nb - 1)];
    }

    float ab[NS][9];
    unsigned long long cd[NS][9];
#pragma unroll
    for (int s = 0; s < NS; s++) {
        float c0, s0, c1, s1, c2, s2, c3, s3;
        __sincosf(x[s].x, &s0, &c0);
        __sincosf(x[s].y, &s1, &c1);
        __sincosf(x[s].z, &s2, &c2);
        __sincosf(x[s].w, &s3, &c3);
        ab[s][0] = 1.f;      ab[s][1] = c1;      ab[s][2] = s1;
        ab[s][3] = c0;       ab[s][4] = c0 * c1; ab[s][5] = c0 * s1;
        ab[s][6] = s0;       ab[s][7] = s0 * c1; ab[s][8] = s0 * s1;
        cd[s][0] = pack_dup(1.f);
        cd[s][1] = pack_dup(c3);
        cd[s][2] = pack_dup(s3);
        cd[s][3] = pack_dup(c2);
        cd[s][4] = pack_dup(c2 * c3);
        cd[s][5] = pack_dup(c2 * s3);
        cd[s][6] = pack_dup(s2);
        cd[s][7] = pack_dup(s2 * c3);
        cd[s][8] = pack_dup(s2 * s3);
    }

    unsigned long long z01[NS], z23[NS];
#pragma unroll
    for (int s = 0; s < NS; s++) { z01[s] = 0ull; z23[s] = 0ull; }

#pragma unroll
    for (int a = 0; a < 9; a++) {
        unsigned long long v01[NS], v23[NS];
#pragma unroll
        for (int s = 0; s < NS; s++) { v01[s] = 0ull; v23[s] = 0ull; }
#pragma unroll
        for (int c = 0; c < 9; c++) {
            ulonglong2 w = cT[a * 9 + c];
#pragma unroll
            for (int s = 0; s < NS; s++) {
                ffma2(v01[s], w.x, cd[s][c]);
                ffma2(v23[s], w.y, cd[s][c]);
            }
        }
#pragma unroll
        for (int s = 0; s < NS; s++) {
            unsigned long long aa = pack_dup(ab[s][a]);
            ffma2(z01[s], aa, v01[s]);
            ffma2(z23[s], aa, v23[s]);
        }
    }

#pragma unroll
    for (int s = 0; s < NS; s++) {
        int b = b0 + s;
        if (b < nb) {
            float z0, z1, z2, z3;
            unpack2(z01[s], z0, z1);
            unpack2(z23[s], z2, z3);
            out[b] = make_float4(z0, z1, z2, z3);
        }
    }
}

// ---------------------------------------------------------------------------
extern "C" void kernel_launch(void* const* d_in, const int* in_sizes, int n_in,
                              void* d_out, int out_size) {
    const float* inputs  = (const float*)d_in[0];
    const float* weights = (const float*)d_in[1];
    if (n_in >= 2 && in_sizes[0] == 24) {  // defensive: identify by size
        weights = (const float*)d_in[0];
        inputs  = (const float*)d_in[1];
    }
    int nb = out_size / 4;  // samples

    // Address of the __constant__ symbol's backing store (query only — no
    // allocation, no stream op). Setup kernel writes T there directly; the
    // constant cache is invalidated at the next launch boundary, so the main
    // kernel sees fresh data (same mechanism cudaMemcpyToSymbol relies on).
    void* cT_addr = nullptr;
    cudaGetSymbolAddress(&cT_addr, cT);

    setup_kernel<<<1, 256>>>(weights, (float4*)cT_addr);

    int groups = (nb + NS - 1) / NS;
    int threads = 128;
    int blocks = (groups + threads - 1) / threads;
    qlayer_kernel<<<blocks, threads>>>((const float4*)inputs, (float4*)d_out, nb);
}